// round 10
// baseline (speedup 1.0000x reference)
#include <cuda_runtime.h>
#include <cuda_fp16.h>
#include <cstddef>
#include <cstdint>

#define NN   50000
#define RR   3
#define EE   800000
#define HIDD 128
#define KK   (RR * HIDD)            // 384
#define SB   256
#define NBLK ((NN + SB - 1) / SB)   // 196
#define LDW  136                    // smem row stride in halves (128 + 8)
#define FUSED_SMEM (2 * 128 * LDW * 2)   // As + Bs, bytes (69632)

// ---------------- static scratch (no cudaMalloc allowed) ----------------
__device__ int    g_outdeg[RR * NN];
__device__ int    g_indeg [RR * NN];
__device__ float  g_rout  [RR * NN];
__device__ float  g_rin   [RR * NN];
__device__ int    g_rowptr[RR * (NN + 1)];
__device__ int    g_cursor[RR * (NN + 1)];
__device__ int    g_bsum  [RR][NBLK];
__device__ int    g_boff  [RR][NBLK];
__device__ int2   g_edge  [RR * EE];                  // (src col, weight bits)
__device__ __half g_hh    [2][(size_t)NN * HIDD];     // layer activations, fp16
__device__ __half g_xh    [(size_t)NN * HIDD];        // fp16 copy of x
__device__ __half g_wt    [5][HIDD][KK];              // transposed fp16 weights [n][k]
__device__ __half g_wtout [64][HIDD];                 // transposed fp16 Wout

// ---------------- preprocessing ----------------
__global__ void zero_deg_kernel() {
    int i = blockIdx.x * blockDim.x + threadIdx.x;
    if (i < RR * NN) { g_outdeg[i] = 0; g_indeg[i] = 0; }
}

__global__ void deg_kernel(const int* __restrict__ src, const int* __restrict__ dst) {
    int i = blockIdx.x * blockDim.x + threadIdx.x;
    if (i >= RR * EE) return;
    int r = i / EE;
    atomicAdd(&g_outdeg[r * NN + src[i]], 1);
    atomicAdd(&g_indeg [r * NN + dst[i]], 1);
}

__global__ void rsqrt_kernel() {
    int i = blockIdx.x * blockDim.x + threadIdx.x;
    if (i >= RR * NN) return;
    g_rout[i] = rsqrtf(fmaxf((float)g_outdeg[i], 1.0f));
    g_rin [i] = rsqrtf(fmaxf((float)g_indeg [i], 1.0f));
}

__global__ void xconv_kernel(const float* __restrict__ x) {
    int i = blockIdx.x * blockDim.x + threadIdx.x;
    if (i < NN * HIDD / 2) {
        float2 v = ((const float2*)x)[i];
        ((__half2*)g_xh)[i] = __floats2half2_rn(v.x, v.y);
    }
}

// transpose + fp16-convert all weights
__global__ void wconv_kernel(const float* __restrict__ W0,
                             const float* __restrict__ Wl,
                             const float* __restrict__ Wout) {
    int i = blockIdx.x * blockDim.x + threadIdx.x;
    const int NW = 5 * HIDD * KK;
    if (i < NW) {
        int L = i / (HIDD * KK);
        int rem = i - L * (HIDD * KK);
        int n = rem / KK;
        int k = rem - n * KK;
        const float* src = (L == 0) ? W0 : (Wl + (size_t)(L - 1) * KK * HIDD);
        g_wt[L][n][k] = __float2half_rn(src[(size_t)k * HIDD + n]);
    } else if (i < NW + 64 * HIDD) {
        int j = i - NW;
        int n = j / HIDD;
        int k = j - n * HIDD;
        g_wtout[n][k] = __float2half_rn(Wout[(size_t)k * 64 + n]);
    }
}

__device__ __forceinline__ int warp_incl_scan(int v, int lane) {
    #pragma unroll
    for (int o = 1; o < 32; o <<= 1) {
        int t = __shfl_up_sync(0xFFFFFFFFu, v, o);
        if (lane >= o) v += t;
    }
    return v;
}

__global__ void scan1_kernel() {
    int r = blockIdx.y, b = blockIdx.x, tid = threadIdx.x;
    int i = b * SB + tid;
    int v = (i < NN) ? g_indeg[r * NN + i] : 0;
    __shared__ int ws[8];
    int lane = tid & 31, wid = tid >> 5;
    #pragma unroll
    for (int o = 16; o > 0; o >>= 1) v += __shfl_down_sync(0xFFFFFFFFu, v, o);
    if (lane == 0) ws[wid] = v;
    __syncthreads();
    if (tid == 0) {
        int s = 0;
        #pragma unroll
        for (int w = 0; w < 8; w++) s += ws[w];
        g_bsum[r][b] = s;
    }
}

__global__ void scan2_kernel() {
    int r = blockIdx.x, tid = threadIdx.x;
    int lane = tid & 31, wid = tid >> 5;
    __shared__ int ws[8];
    int v = (tid < NBLK) ? g_bsum[r][tid] : 0;
    int incl = warp_incl_scan(v, lane);
    if (lane == 31) ws[wid] = incl;
    __syncthreads();
    if (wid == 0) {
        int t = (lane < 8) ? ws[lane] : 0;
        t = warp_incl_scan(t, lane);
        if (lane < 8) ws[lane] = t;
    }
    __syncthreads();
    incl += (wid > 0) ? ws[wid - 1] : 0;
    if (tid < NBLK) g_boff[r][tid] = incl - v;
    if (tid == 255) g_rowptr[r * (NN + 1) + NN] = incl;
}

__global__ void scan3_kernel() {
    int r = blockIdx.y, b = blockIdx.x, tid = threadIdx.x;
    int lane = tid & 31, wid = tid >> 5;
    __shared__ int ws[8];
    int i = b * SB + tid;
    int v = (i < NN) ? g_indeg[r * NN + i] : 0;
    int incl = warp_incl_scan(v, lane);
    if (lane == 31) ws[wid] = incl;
    __syncthreads();
    if (wid == 0) {
        int t = (lane < 8) ? ws[lane] : 0;
        t = warp_incl_scan(t, lane);
        if (lane < 8) ws[lane] = t;
    }
    __syncthreads();
    incl += (wid > 0) ? ws[wid - 1] : 0;
    int excl = g_boff[r][b] + incl - v;
    if (i < NN) {
        g_rowptr[r * (NN + 1) + i] = excl;
        g_cursor[r * (NN + 1) + i] = excl;
    }
}

__global__ void fill_kernel(const int* __restrict__ src, const int* __restrict__ dst) {
    int i = blockIdx.x * blockDim.x + threadIdx.x;
    if (i >= RR * EE) return;
    int r = i / EE;
    int d = dst[i];
    int s = src[i];
    int pos = atomicAdd(&g_cursor[r * (NN + 1) + d], 1);
    g_edge[(size_t)r * EE + pos] = make_int2(s, __float_as_int(g_rout[r * NN + s]));
}

// ---------------- gather one dst row (warp-collective, MLP-8) ----------------
__device__ __forceinline__ float4 gather_row(const uint2* __restrict__ h2,
                                             const int2* __restrict__ edges,
                                             int start, int end, int lane) {
    float4 acc = make_float4(0.f, 0.f, 0.f, 0.f);
    int e = start;
    #pragma unroll 1
    for (; e + 8 <= end; e += 8) {
        int2 ed[8];
        #pragma unroll
        for (int j = 0; j < 8; j++) ed[j] = edges[e + j];
        uint2 u[8];
        #pragma unroll
        for (int j = 0; j < 8; j++) u[j] = h2[(size_t)ed[j].x * 32 + lane];
        #pragma unroll
        for (int j = 0; j < 8; j++) {
            float w = __int_as_float(ed[j].y);
            float2 a = __half22float2(*(__half2*)&u[j].x);
            float2 b = __half22float2(*(__half2*)&u[j].y);
            acc.x = fmaf(w, a.x, acc.x); acc.y = fmaf(w, a.y, acc.y);
            acc.z = fmaf(w, b.x, acc.z); acc.w = fmaf(w, b.y, acc.w);
        }
    }
    if (e + 4 <= end) {
        int2 ed[4];
        #pragma unroll
        for (int j = 0; j < 4; j++) ed[j] = edges[e + j];
        uint2 u[4];
        #pragma unroll
        for (int j = 0; j < 4; j++) u[j] = h2[(size_t)ed[j].x * 32 + lane];
        #pragma unroll
        for (int j = 0; j < 4; j++) {
            float w = __int_as_float(ed[j].y);
            float2 a = __half22float2(*(__half2*)&u[j].x);
            float2 b = __half22float2(*(__half2*)&u[j].y);
            acc.x = fmaf(w, a.x, acc.x); acc.y = fmaf(w, a.y, acc.y);
            acc.z = fmaf(w, b.x, acc.z); acc.w = fmaf(w, b.y, acc.w);
        }
        e += 4;
    }
    for (; e < end; e++) {
        int2 ed = edges[e];
        float w = __int_as_float(ed.y);
        uint2 u = h2[(size_t)ed.x * 32 + lane];
        float2 a = __half22float2(*(__half2*)&u.x), b = __half22float2(*(__half2*)&u.y);
        acc.x = fmaf(w, a.x, acc.x); acc.y = fmaf(w, a.y, acc.y);
        acc.z = fmaf(w, b.x, acc.z); acc.w = fmaf(w, b.y, acc.w);
    }
    return acc;
}

// ---------------- mma helpers ----------------
__device__ __forceinline__ void mma_f16(float* c, const uint32_t* a,
                                        uint32_t b0, uint32_t b1) {
    asm volatile(
        "mma.sync.aligned.m16n8k16.row.col.f32.f16.f16.f32 "
        "{%0,%1,%2,%3}, {%4,%5,%6,%7}, {%8,%9}, {%0,%1,%2,%3};"
        : "+f"(c[0]), "+f"(c[1]), "+f"(c[2]), "+f"(c[3])
        : "r"(a[0]), "r"(a[1]), "r"(a[2]), "r"(a[3]), "r"(b0), "r"(b1));
}

__device__ __forceinline__ void ldsm_x4(uint32_t* d, uint32_t addr) {
    asm volatile("ldmatrix.sync.aligned.m8n8.x4.shared.b16 {%0,%1,%2,%3}, [%4];"
                 : "=r"(d[0]), "=r"(d[1]), "=r"(d[2]), "=r"(d[3]) : "r"(addr));
}

__device__ __forceinline__ void ldsm_x2(uint32_t& d0, uint32_t& d1, uint32_t addr) {
    asm volatile("ldmatrix.sync.aligned.m8n8.x2.shared.b16 {%0,%1}, [%2];"
                 : "=r"(d0), "=r"(d1) : "r"(addr));
}

// ---------------- fused layer: SpMM (per relation, into smem) + GEMM ----------------
// h_out[n] = leaky(( sum_r (A_r h)[n] @ W_r + sum_r b_r ) / 3)
// in_sel: -1 -> g_xh, 0/1 -> g_hh.  wsel: 0..4.  o_sel: 0/1 -> g_hh[o_sel].
__global__ __launch_bounds__(256)
void fused_layer_kernel(int in_sel, int wsel, const float* __restrict__ bias,
                        int o_sel, int leaky) {
    extern __shared__ __half smf[];
    __half* As = smf;               // [128][LDW]
    __half* Bs = smf + 128 * LDW;   // [128][LDW]

    const __half* hin = (in_sel < 0) ? g_xh : g_hh[in_sel];
    const uint2* h2 = (const uint2*)hin;
    const __half* Wt = &g_wt[wsel][0][0];
    __half* Hout = g_hh[o_sel];

    int tid  = threadIdx.x;
    int wid  = tid >> 5;
    int lane = tid & 31;
    int g    = lane >> 2;
    int tg   = lane & 3;
    int wm   = wid >> 2;            // 0..1
    int wn   = wid & 3;             // 0..3
    int blockRow = blockIdx.x * 128;

    uint32_t as_base = (uint32_t)__cvta_generic_to_shared(As);
    uint32_t bs_base = (uint32_t)__cvta_generic_to_shared(Bs);

    int a_row = wm * 64 + (lane & 15);
    int a_col = (lane >> 4) * 8;
    int b_row = wn * 32 + (lane & 7);
    int b_col = ((lane >> 3) & 1) * 8;

    float acc[4][4][4];
    #pragma unroll
    for (int i = 0; i < 4; i++)
        #pragma unroll
        for (int j = 0; j < 4; j++)
            #pragma unroll
            for (int q = 0; q < 4; q++) acc[i][j][q] = 0.f;

    for (int r = 0; r < RR; r++) {
        // stage weight slice Bs[n][k] = Wt[n][r*128+k]
        #pragma unroll
        for (int i = 0; i < 8; i++) {
            int v = tid + i * 256;
            int n = v >> 4, kq = v & 15;
            *(uint4*)&Bs[n * LDW + kq * 8] =
                *(const uint4*)(Wt + (size_t)n * KK + r * HIDD + kq * 8);
        }
        // gather 128 dst rows for relation r into As
        const int2* edges = g_edge + (size_t)r * EE;
        #pragma unroll 1
        for (int rr = 0; rr < 16; rr++) {
            int row = wid * 16 + rr;
            int dst = blockRow + row;
            uint2 o = make_uint2(0, 0);
            if (dst < NN) {
                int base = r * (NN + 1) + dst;
                int start = g_rowptr[base];
                int end   = g_rowptr[base + 1];
                float4 a = gather_row(h2, edges, start, end, lane);
                float ri = g_rin[r * NN + dst];
                *(__half2*)&o.x = __floats2half2_rn(a.x * ri, a.y * ri);
                *(__half2*)&o.y = __floats2half2_rn(a.z * ri, a.w * ri);
            }
            *(uint2*)&As[row * LDW + lane * 4] = o;
        }
        __syncthreads();

        // mma over this 128-wide k chunk
        #pragma unroll
        for (int kk = 0; kk < 8; kk++) {
            int kb = kk * 16;
            uint32_t af[4][4];
            #pragma unroll
            for (int mt = 0; mt < 4; mt++) {
                uint32_t addr = as_base +
                    (uint32_t)(((a_row + mt * 16) * LDW + kb + a_col) * 2);
                ldsm_x4(af[mt], addr);
            }
            #pragma unroll
            for (int nt = 0; nt < 4; nt++) {
                uint32_t b0, b1;
                uint32_t addr = bs_base +
                    (uint32_t)(((b_row + nt * 8) * LDW + kb + b_col) * 2);
                ldsm_x2(b0, b1, addr);
                #pragma unroll
                for (int mt = 0; mt < 4; mt++)
                    mma_f16(acc[mt][nt], af[mt], b0, b1);
            }
        }
        __syncthreads();
    }

    // ---- epilogue: mean over relations + bias + leaky -> fp16 h ----
    const float alpha = 1.0f / (float)RR;
    float2 bsv[4];
    #pragma unroll
    for (int nt = 0; nt < 4; nt++) {
        int col = wn * 32 + nt * 8 + tg * 2;
        float sx = 0.f, sy = 0.f;
        #pragma unroll
        for (int rr = 0; rr < RR; rr++) {
            sx += bias[rr * HIDD + col];
            sy += bias[rr * HIDD + col + 1];
        }
        bsv[nt].x = sx; bsv[nt].y = sy;
    }
    #pragma unroll
    for (int mt = 0; mt < 4; mt++) {
        int r0 = blockRow + wm * 64 + mt * 16 + g;
        int r1 = r0 + 8;
        #pragma unroll
        for (int nt = 0; nt < 4; nt++) {
            int col = wn * 32 + nt * 8 + tg * 2;
            float v0 = (acc[mt][nt][0] + bsv[nt].x) * alpha;
            float v1 = (acc[mt][nt][1] + bsv[nt].y) * alpha;
            float v2 = (acc[mt][nt][2] + bsv[nt].x) * alpha;
            float v3 = (acc[mt][nt][3] + bsv[nt].y) * alpha;
            if (leaky) {
                if (v0 < 0.f) v0 *= 0.01f;
                if (v1 < 0.f) v1 *= 0.01f;
                if (v2 < 0.f) v2 *= 0.01f;
                if (v3 < 0.f) v3 *= 0.01f;
            }
            if (r0 < NN) *(__half2*)(Hout + (size_t)r0 * HIDD + col) = __floats2half2_rn(v0, v1);
            if (r1 < NN) *(__half2*)(Hout + (size_t)r1 * HIDD + col) = __floats2half2_rn(v2, v3);
        }
    }
}

// ---------------- final linear: out[N,64] = h @ Wout + bout (fp32 out) ----------------
__global__ __launch_bounds__(128)
void gemm_out_kernel(int a_sel, const float* __restrict__ bias,
                     float* __restrict__ Cext) {
    const int BN = 64, BK = 64, PAD = 8, LDWO = BK + PAD;
    const __half* A  = g_hh[a_sel];
    const __half* Wt = &g_wtout[0][0];

    __shared__ __half As[128][LDWO];
    __shared__ __half Bs[BN][LDWO];

    int tid  = threadIdx.x;
    int wid  = tid >> 5;
    int lane = tid & 31;
    int g    = lane >> 2;
    int tg   = lane & 3;
    int wm   = wid >> 1;
    int wn   = wid & 1;
    int blockRow = blockIdx.x * 128;

    uint32_t as_base = (uint32_t)__cvta_generic_to_shared(&As[0][0]);
    uint32_t bs_base = (uint32_t)__cvta_generic_to_shared(&Bs[0][0]);

    int a_row = wm * 64 + (lane & 15);
    int a_col = (lane >> 4) * 8;
    int b_row = wn * 32 + (lane & 7);
    int b_col = ((lane >> 3) & 1) * 8;

    float acc[4][4][4];
    #pragma unroll
    for (int i = 0; i < 4; i++)
        #pragma unroll
        for (int j = 0; j < 4; j++)
            #pragma unroll
            for (int q = 0; q < 4; q++) acc[i][j][q] = 0.f;

    for (int k0 = 0; k0 < HIDD; k0 += BK) {
        #pragma unroll
        for (int i = 0; i < 8; i++) {
            int v = tid + i * 128;
            int row = v >> 3, kq = v & 7;
            int gr = blockRow + row;
            uint4 val = make_uint4(0, 0, 0, 0);
            if (gr < NN) val = *(const uint4*)(A + (size_t)gr * HIDD + k0 + kq * 8);
            *(uint4*)&As[row][kq * 8] = val;
        }
        #pragma unroll
        for (int i = 0; i < 4; i++) {
            int v = tid + i * 128;
            int n = v >> 3, kq = v & 7;
            *(uint4*)&Bs[n][kq * 8] = *(const uint4*)(Wt + (size_t)n * HIDD + k0 + kq * 8);
        }
        __syncthreads();
        #pragma unroll
        for (int kk = 0; kk < BK / 16; kk++) {
            int kb = kk * 16;
            uint32_t af[4][4];
            #pragma unroll
            for (int mt = 0; mt < 4; mt++) {
                uint32_t addr = as_base +
                    (uint32_t)(((a_row + mt * 16) * LDWO + kb + a_col) * 2);
                ldsm_x4(af[mt], addr);
            }
            #pragma unroll
            for (int nt = 0; nt < 4; nt++) {
                uint32_t b0, b1;
                uint32_t addr = bs_base +
                    (uint32_t)(((b_row + nt * 8) * LDWO + kb + b_col) * 2);
                ldsm_x2(b0, b1, addr);
                #pragma unroll
                for (int mt = 0; mt < 4; mt++)
                    mma_f16(acc[mt][nt], af[mt], b0, b1);
            }
        }
        __syncthreads();
    }

    float2 bsv[4];
    #pragma unroll
    for (int nt = 0; nt < 4; nt++) {
        int col = wn * 32 + nt * 8 + tg * 2;
        bsv[nt].x = bias[col];
        bsv[nt].y = bias[col + 1];
    }
    #pragma unroll
    for (int mt = 0; mt < 4; mt++) {
        int r0 = blockRow + wm * 64 + mt * 16 + g;
        int r1 = r0 + 8;
        #pragma unroll
        for (int nt = 0; nt < 4; nt++) {
            int col = wn * 32 + nt * 8 + tg * 2;
            float v0 = acc[mt][nt][0] + bsv[nt].x;
            float v1 = acc[mt][nt][1] + bsv[nt].y;
            float v2 = acc[mt][nt][2] + bsv[nt].x;
            float v3 = acc[mt][nt][3] + bsv[nt].y;
            if (r0 < NN) *(float2*)(Cext + (size_t)r0 * 64 + col) = make_float2(v0, v1);
            if (r1 < NN) *(float2*)(Cext + (size_t)r1 * 64 + col) = make_float2(v2, v3);
        }
    }
}

// ---------------- launcher ----------------
extern "C" void kernel_launch(void* const* d_in, const int* in_sizes, int n_in,
                              void* d_out, int out_size) {
    const float* x    = (const float*)d_in[0];
    const int*   esrc = (const int*)  d_in[1];
    const int*   edst = (const int*)  d_in[2];
    const float* W0   = (const float*)d_in[3];
    const float* b0   = (const float*)d_in[4];
    const float* Wl   = (const float*)d_in[5];
    const float* bl   = (const float*)d_in[6];
    const float* Wout = (const float*)d_in[7];
    const float* bout = (const float*)d_in[8];
    float* out = (float*)d_out;

    cudaFuncSetAttribute(fused_layer_kernel,
                         cudaFuncAttributeMaxDynamicSharedMemorySize, FUSED_SMEM);

    zero_deg_kernel<<<(RR * NN + 255) / 256, 256>>>();
    xconv_kernel<<<(NN * HIDD / 2 + 255) / 256, 256>>>(x);
    wconv_kernel<<<(5 * HIDD * KK + 64 * HIDD + 255) / 256, 256>>>(W0, Wl, Wout);
    deg_kernel<<<(RR * EE + 255) / 256, 256>>>(esrc, edst);
    rsqrt_kernel<<<(RR * NN + 255) / 256, 256>>>();
    scan1_kernel<<<dim3(NBLK, RR), SB>>>();
    scan2_kernel<<<RR, 256>>>();
    scan3_kernel<<<dim3(NBLK, RR), SB>>>();
    fill_kernel<<<(RR * EE + 255) / 256, 256>>>(esrc, edst);

    const int blocks = (NN + 127) / 128;   // 391

    // 5 fused layers: in: x,h0,h1,h0,h1 ; out: h0,h1,h0,h1,h0 ; leaky except last
    fused_layer_kernel<<<blocks, 256, FUSED_SMEM>>>(-1, 0, b0, 0, 1);
    for (int l = 0; l < 4; l++) {
        fused_layer_kernel<<<blocks, 256, FUSED_SMEM>>>(
            (l & 1) ? 1 : 0, l + 1, bl + (size_t)l * RR * HIDD,
            (l & 1) ? 0 : 1, (l != 3) ? 1 : 0);
    }
    // final linear (h in g_hh[0] after layer 4)
    gemm_out_kernel<<<blocks, 128>>>(0, bout, out);
}

// round 12
// speedup vs baseline: 1.6632x; 1.6632x over previous
#include <cuda_runtime.h>
#include <cuda_fp16.h>
#include <cstddef>
#include <cstdint>

#define NN   50000
#define RR   3
#define EE   800000
#define HIDD 128
#define KK   (RR * HIDD)            // 384
#define SB   256
#define NBLK ((NN + SB - 1) / SB)   // 196

// ---------------- static scratch (no cudaMalloc allowed) ----------------
__device__ int    g_outdeg[RR * NN];
__device__ int    g_indeg [RR * NN];
__device__ float  g_rout  [RR * NN];
__device__ float  g_rin   [RR * NN];
__device__ int    g_rowptr[RR * (NN + 1)];
__device__ int    g_cursor[RR * (NN + 1)];
__device__ int    g_bsum  [RR][NBLK];
__device__ int2   g_edge  [RR * EE];                  // (src col, weight bits)
__device__ __half g_zh    [(size_t)NN * KK];          // SpMM output (GEMM A), fp16
__device__ __half g_hh    [2][(size_t)NN * HIDD];     // layer activations, fp16
__device__ __half g_xh    [(size_t)NN * HIDD];        // fp16 copy of x
__device__ __half g_wt    [4][HIDD][KK];              // transposed fp16 weights [n][k], layers 0-3
__device__ __half g_wcmb  [64][KK];                   // combined (W4 @ Wout / 3)^T fp16
__device__ float  g_bcmb  [64];                       // combined bias for final output

// ---------------- prep: zero degs + x->fp16 + weight transpose/convert + Wcomb ----------------
__global__ void prep_kernel(const float* __restrict__ x,
                            const float* __restrict__ W0,
                            const float* __restrict__ Wl,
                            const float* __restrict__ bl,
                            const float* __restrict__ Wout,
                            const float* __restrict__ bout) {
    int i = blockIdx.x * blockDim.x + threadIdx.x;
    if (i < NN * HIDD / 2) {
        float2 v = ((const float2*)x)[i];
        ((__half2*)g_xh)[i] = __floats2half2_rn(v.x, v.y);
    }
    if (i < RR * NN) { g_outdeg[i] = 0; g_indeg[i] = 0; }
    if (i < 4 * HIDD * KK) {
        int L = i / (HIDD * KK);
        int rem = i - L * (HIDD * KK);
        int n = rem / KK;
        int k = rem - n * KK;
        const float* src = (L == 0) ? W0 : (Wl + (size_t)(L - 1) * KK * HIDD);
        g_wt[L][n][k] = __float2half_rn(src[(size_t)k * HIDD + n]);
    }
    if (i < 64 * KK) {
        // Wcomb[n][k] = (1/3) * sum_j W4[k][j] * Wout[j][n]
        int n = i / KK;
        int k = i - n * KK;
        const float* W4 = Wl + (size_t)3 * KK * HIDD;   // [384][128]
        float s = 0.f;
        #pragma unroll 4
        for (int j = 0; j < HIDD; j++)
            s = fmaf(W4[(size_t)k * HIDD + j], Wout[(size_t)j * 64 + n], s);
        g_wcmb[n][k] = __float2half_rn(s * (1.0f / 3.0f));
    }
    if (i < 64) {
        // bcomb[n] = (sum_r b4_r /3) @ Wout[:,n] + bout[n]
        const float* b4 = bl + (size_t)3 * RR * HIDD;
        float s = 0.f;
        for (int j = 0; j < HIDD; j++) {
            float bj = (b4[j] + b4[HIDD + j] + b4[2 * HIDD + j]) * (1.0f / 3.0f);
            s = fmaf(bj, Wout[(size_t)j * 64 + i], s);
        }
        g_bcmb[i] = s + bout[i];
    }
}

__global__ void deg_kernel(const int* __restrict__ src, const int* __restrict__ dst) {
    int i = blockIdx.x * blockDim.x + threadIdx.x;
    if (i >= RR * EE) return;
    int r = i / EE;
    atomicAdd(&g_outdeg[r * NN + src[i]], 1);
    atomicAdd(&g_indeg [r * NN + dst[i]], 1);
}

__device__ __forceinline__ int warp_incl_scan(int v, int lane) {
    #pragma unroll
    for (int o = 1; o < 32; o <<= 1) {
        int t = __shfl_up_sync(0xFFFFFFFFu, v, o);
        if (lane >= o) v += t;
    }
    return v;
}

// per-block degree sums + rsqrt norms
__global__ void scanA_kernel() {
    int r = blockIdx.y, b = blockIdx.x, tid = threadIdx.x;
    int i = b * SB + tid;
    int v = 0;
    if (i < NN) {
        int od = g_outdeg[r * NN + i];
        int id = g_indeg [r * NN + i];
        g_rout[r * NN + i] = rsqrtf(fmaxf((float)od, 1.0f));
        g_rin [r * NN + i] = rsqrtf(fmaxf((float)id, 1.0f));
        v = id;
    }
    __shared__ int ws[8];
    int lane = tid & 31, wid = tid >> 5;
    #pragma unroll
    for (int o = 16; o > 0; o >>= 1) v += __shfl_down_sync(0xFFFFFFFFu, v, o);
    if (lane == 0) ws[wid] = v;
    __syncthreads();
    if (tid == 0) {
        int s = 0;
        #pragma unroll
        for (int w = 0; w < 8; w++) s += ws[w];
        g_bsum[r][b] = s;
    }
}

// local scan + inline prefix of block sums -> rowptr, cursor
__global__ void scanB_kernel() {
    int r = blockIdx.y, b = blockIdx.x, tid = threadIdx.x;
    int lane = tid & 31, wid = tid >> 5;
    __shared__ int ws[8];
    __shared__ int s_boff;
    // warp 0: prefix sum of bsum[r][0..b)
    if (wid == 0) {
        int s = 0;
        for (int i = lane; i < b; i += 32) s += g_bsum[r][i];
        #pragma unroll
        for (int o = 16; o > 0; o >>= 1) s += __shfl_down_sync(0xFFFFFFFFu, s, o);
        if (lane == 0) s_boff = s;
    }
    int i = b * SB + tid;
    int v = (i < NN) ? g_indeg[r * NN + i] : 0;
    int incl = warp_incl_scan(v, lane);
    if (lane == 31) ws[wid] = incl;
    __syncthreads();
    if (wid == 0) {
        int t = (lane < 8) ? ws[lane] : 0;
        t = warp_incl_scan(t, lane);
        if (lane < 8) ws[lane] = t;
    }
    __syncthreads();
    incl += (wid > 0) ? ws[wid - 1] : 0;
    int excl = s_boff + incl - v;
    if (i < NN) {
        g_rowptr[r * (NN + 1) + i] = excl;
        g_cursor[r * (NN + 1) + i] = excl;
    }
    if (b == NBLK - 1 && tid == SB - 1)
        g_rowptr[r * (NN + 1) + NN] = s_boff + incl;
}

__global__ void fill_kernel(const int* __restrict__ src, const int* __restrict__ dst) {
    int i = blockIdx.x * blockDim.x + threadIdx.x;
    if (i >= RR * EE) return;
    int r = i / EE;
    int d = dst[i];
    int s = src[i];
    int pos = atomicAdd(&g_cursor[r * (NN + 1) + d], 1);
    g_edge[(size_t)r * EE + pos] = make_int2(s, __float_as_int(g_rout[r * NN + s]));
}

// ---------------- SpMM: one warp per (relation, dst-row), MLP-8 fp16 gather ----------------
__global__ void spmm_kernel(int in_sel) {
    int gw   = (blockIdx.x * blockDim.x + threadIdx.x) >> 5;
    int lane = threadIdx.x & 31;
    if (gw >= RR * NN) return;
    int r = gw / NN;
    int n = gw - r * NN;

    const __half* hin = (in_sel < 0) ? g_xh : g_hh[in_sel];
    const uint2* h2 = (const uint2*)hin;
    const int2* edges = g_edge + (size_t)r * EE;

    int start = g_rowptr[r * (NN + 1) + n];
    int end   = g_rowptr[r * (NN + 1) + n + 1];

    float4 acc = make_float4(0.f, 0.f, 0.f, 0.f);
    int e = start;
    #pragma unroll 1
    for (; e + 8 <= end; e += 8) {
        int2 ed[8];
        #pragma unroll
        for (int j = 0; j < 8; j++) ed[j] = edges[e + j];
        uint2 u[8];
        #pragma unroll
        for (int j = 0; j < 8; j++) u[j] = h2[(size_t)ed[j].x * 32 + lane];
        #pragma unroll
        for (int j = 0; j < 8; j++) {
            float w = __int_as_float(ed[j].y);
            float2 a = __half22float2(*(__half2*)&u[j].x);
            float2 b = __half22float2(*(__half2*)&u[j].y);
            acc.x = fmaf(w, a.x, acc.x); acc.y = fmaf(w, a.y, acc.y);
            acc.z = fmaf(w, b.x, acc.z); acc.w = fmaf(w, b.y, acc.w);
        }
    }
    if (e + 4 <= end) {
        int2 ed[4];
        #pragma unroll
        for (int j = 0; j < 4; j++) ed[j] = edges[e + j];
        uint2 u[4];
        #pragma unroll
        for (int j = 0; j < 4; j++) u[j] = h2[(size_t)ed[j].x * 32 + lane];
        #pragma unroll
        for (int j = 0; j < 4; j++) {
            float w = __int_as_float(ed[j].y);
            float2 a = __half22float2(*(__half2*)&u[j].x);
            float2 b = __half22float2(*(__half2*)&u[j].y);
            acc.x = fmaf(w, a.x, acc.x); acc.y = fmaf(w, a.y, acc.y);
            acc.z = fmaf(w, b.x, acc.z); acc.w = fmaf(w, b.y, acc.w);
        }
        e += 4;
    }
    for (; e < end; e++) {
        int2 ed = edges[e];
        float w = __int_as_float(ed.y);
        uint2 u = h2[(size_t)ed.x * 32 + lane];
        float2 a = __half22float2(*(__half2*)&u.x), b = __half22float2(*(__half2*)&u.y);
        acc.x = fmaf(w, a.x, acc.x); acc.y = fmaf(w, a.y, acc.y);
        acc.z = fmaf(w, b.x, acc.z); acc.w = fmaf(w, b.y, acc.w);
    }
    float ri = g_rin[r * NN + n];
    uint2 o;
    *(__half2*)&o.x = __floats2half2_rn(acc.x * ri, acc.y * ri);
    *(__half2*)&o.y = __floats2half2_rn(acc.z * ri, acc.w * ri);
    ((uint2*)g_zh)[((size_t)n * RR + r) * 32 + lane] = o;
}

// ---------------- fp16 tensor-core GEMM (m16n8k16 + ldmatrix) ----------------
__device__ __forceinline__ void mma_f16(float* c, const uint32_t* a,
                                        uint32_t b0, uint32_t b1) {
    asm volatile(
        "mma.sync.aligned.m16n8k16.row.col.f32.f16.f16.f32 "
        "{%0,%1,%2,%3}, {%4,%5,%6,%7}, {%8,%9}, {%0,%1,%2,%3};"
        : "+f"(c[0]), "+f"(c[1]), "+f"(c[2]), "+f"(c[3])
        : "r"(a[0]), "r"(a[1]), "r"(a[2]), "r"(a[3]), "r"(b0), "r"(b1));
}

__device__ __forceinline__ void ldsm_x4(uint32_t* d, uint32_t addr) {
    asm volatile("ldmatrix.sync.aligned.m8n8.x4.shared.b16 {%0,%1,%2,%3}, [%4];"
                 : "=r"(d[0]), "=r"(d[1]), "=r"(d[2]), "=r"(d[3]) : "r"(addr));
}

__device__ __forceinline__ void ldsm_x2(uint32_t& d0, uint32_t& d1, uint32_t addr) {
    asm volatile("ldmatrix.sync.aligned.m8n8.x2.shared.b16 {%0,%1}, [%2];"
                 : "=r"(d0), "=r"(d1) : "r"(addr));
}

// C[M,BN] = (A[M,K] @ Wt^T + bias) * alpha.
// wsel: 0..3 -> g_wt[wsel] (BN=128), 4 -> g_wcmb (BN=64).
// bias_sel: >=0 -> sum rows of passed bias ptr (biasRows rows of BN), -1 -> g_bcmb.
// o_sel: 0/1 -> g_hh[o_sel] (fp16), 2 -> Cext (fp32).
template <int BN, int WN, int NT>
__global__ __launch_bounds__(NT)
void gemm_tc_kernel(int wsel,
                    const float* __restrict__ bias, int biasRows, int bias_sel,
                    int o_sel, float* __restrict__ Cext,
                    float alpha, int leaky) {
    const int BM = 128, BK = 64, PAD = 8, LDW = BK + PAD;   // 72 halves
    const int K = KK;
    const __half* A  = g_zh;
    const __half* Wt = (wsel < 4) ? &g_wt[wsel][0][0] : &g_wcmb[0][0];
    __half* Hout = (o_sel == 2) ? nullptr : g_hh[o_sel];
    const float* bptr = (bias_sel < 0) ? g_bcmb : bias;

    __shared__ __half As[BM][LDW];
    __shared__ __half Bs[BN][LDW];

    int tid  = threadIdx.x;
    int wid  = tid >> 5;
    int lane = tid & 31;
    int g    = lane >> 2;
    int tg   = lane & 3;
    int wm   = wid / WN;
    int wn   = wid % WN;
    int blockRow = blockIdx.x * BM;

    uint32_t as_base = (uint32_t)__cvta_generic_to_shared(&As[0][0]);
    uint32_t bs_base = (uint32_t)__cvta_generic_to_shared(&Bs[0][0]);

    int a_row = wm * 64 + (lane & 15);
    int a_col = (lane >> 4) * 8;
    int b_row = wn * 32 + (lane & 7);
    int b_col = ((lane >> 3) & 1) * 8;

    float acc[4][4][4];
    #pragma unroll
    for (int i = 0; i < 4; i++)
        #pragma unroll
        for (int j = 0; j < 4; j++)
            #pragma unroll
            for (int q = 0; q < 4; q++) acc[i][j][q] = 0.f;

    const int ASLOT = BM * (BK / 8);
    const int BSLOT = BN * (BK / 8);

    for (int k0 = 0; k0 < K; k0 += BK) {
        #pragma unroll
        for (int i = 0; i < ASLOT / NT; i++) {
            int v = tid + i * NT;
            int row = v >> 3, kq = v & 7;
            int gr = blockRow + row;
            uint4 val = make_uint4(0, 0, 0, 0);
            if (gr < NN) val = *(const uint4*)(A + (size_t)gr * K + k0 + kq * 8);
            *(uint4*)&As[row][kq * 8] = val;
        }
        #pragma unroll
        for (int i = 0; i < BSLOT / NT; i++) {
            int v = tid + i * NT;
            int n = v >> 3, kq = v & 7;
            *(uint4*)&Bs[n][kq * 8] = *(const uint4*)(Wt + (size_t)n * K + k0 + kq * 8);
        }
        __syncthreads();

        #pragma unroll
        for (int kk = 0; kk < BK / 16; kk++) {
            int kb = kk * 16;
            uint32_t af[4][4];
            #pragma unroll
            for (int mt = 0; mt < 4; mt++) {
                uint32_t addr = as_base +
                    (uint32_t)(((a_row + mt * 16) * LDW + kb + a_col) * 2);
                ldsm_x4(af[mt], addr);
            }
            #pragma unroll
            for (int nt = 0; nt < 4; nt++) {
                uint32_t b0, b1;
                uint32_t addr = bs_base +
                    (uint32_t)(((b_row + nt * 8) * LDW + kb + b_col) * 2);
                ldsm_x2(b0, b1, addr);
                #pragma unroll
                for (int mt = 0; mt < 4; mt++)
                    mma_f16(acc[mt][nt], af[mt], b0, b1);
            }
        }
        __syncthreads();
    }

    // ---- epilogue ----
    float2 bs[4];
    #pragma unroll
    for (int nt = 0; nt < 4; nt++) {
        int col = wn * 32 + nt * 8 + tg * 2;
        float sx = 0.f, sy = 0.f;
        for (int rr = 0; rr < biasRows; rr++) {
            sx += bptr[rr * BN + col];
            sy += bptr[rr * BN + col + 1];
        }
        bs[nt].x = sx; bs[nt].y = sy;
    }
    #pragma unroll
    for (int mt = 0; mt < 4; mt++) {
        int r0 = blockRow + wm * 64 + mt * 16 + g;
        int r1 = r0 + 8;
        #pragma unroll
        for (int nt = 0; nt < 4; nt++) {
            int col = wn * 32 + nt * 8 + tg * 2;
            float v0 = (acc[mt][nt][0] + bs[nt].x) * alpha;
            float v1 = (acc[mt][nt][1] + bs[nt].y) * alpha;
            float v2 = (acc[mt][nt][2] + bs[nt].x) * alpha;
            float v3 = (acc[mt][nt][3] + bs[nt].y) * alpha;
            if (leaky) {
                if (v0 < 0.f) v0 *= 0.01f;
                if (v1 < 0.f) v1 *= 0.01f;
                if (v2 < 0.f) v2 *= 0.01f;
                if (v3 < 0.f) v3 *= 0.01f;
            }
            if (o_sel == 2) {
                if (r0 < NN) *(float2*)(Cext + (size_t)r0 * BN + col) = make_float2(v0, v1);
                if (r1 < NN) *(float2*)(Cext + (size_t)r1 * BN + col) = make_float2(v2, v3);
            } else {
                if (r0 < NN) *(__half2*)(Hout + (size_t)r0 * HIDD + col) = __floats2half2_rn(v0, v1);
                if (r1 < NN) *(__half2*)(Hout + (size_t)r1 * HIDD + col) = __floats2half2_rn(v2, v3);
            }
        }
    }
}

// ---------------- launcher ----------------
extern "C" void kernel_launch(void* const* d_in, const int* in_sizes, int n_in,
                              void* d_out, int out_size) {
    const float* x    = (const float*)d_in[0];
    const int*   esrc = (const int*)  d_in[1];
    const int*   edst = (const int*)  d_in[2];
    const float* W0   = (const float*)d_in[3];
    const float* b0   = (const float*)d_in[4];
    const float* Wl   = (const float*)d_in[5];
    const float* bl   = (const float*)d_in[6];
    const float* Wout = (const float*)d_in[7];
    const float* bout = (const float*)d_in[8];
    float* out = (float*)d_out;

    // launch 0-4: preprocessing (spmm lands at index 5 for the ncu window)
    prep_kernel<<<(NN * HIDD / 2 + 255) / 256, 256>>>(x, W0, Wl, bl, Wout, bout);
    deg_kernel<<<(RR * EE + 255) / 256, 256>>>(esrc, edst);
    scanA_kernel<<<dim3(NBLK, RR), SB>>>();
    scanB_kernel<<<dim3(NBLK, RR), SB>>>();
    fill_kernel<<<(RR * EE + 255) / 256, 256>>>(esrc, edst);

    const int spmm_blocks = (RR * NN * 32 + 255) / 256;
    const int gemm_blocks = (NN + 127) / 128;   // 391
    const float inv_r = 1.0f / (float)RR;

    // conv layers 0..3 -> h, leaky
    spmm_kernel<<<spmm_blocks, 256>>>(-1);
    gemm_tc_kernel<128, 4, 256><<<gemm_blocks, 256>>>(
        0, b0, RR, 0, 0, nullptr, inv_r, 1);
    for (int l = 0; l < 3; l++) {
        spmm_kernel<<<spmm_blocks, 256>>>(l & 1 ? 1 : 0);
        gemm_tc_kernel<128, 4, 256><<<gemm_blocks, 256>>>(
            l + 1, bl + (size_t)l * RR * HIDD, RR, 0,
            (l & 1) ? 0 : 1, nullptr, inv_r, 1);
    }
    // conv layer 4 + final linear folded: z5 @ Wcomb + bcomb -> out (fp32)
    spmm_kernel<<<spmm_blocks, 256>>>(1);
    gemm_tc_kernel<64, 2, 128><<<gemm_blocks, 128>>>(
        4, nullptr, 1, -1, 2, out, 1.0f, 0);
}